// round 1
// baseline (speedup 1.0000x reference)
#include <cuda_runtime.h>

// Encoding layer: B=32, C=256, N=4096 tokens, K=32 codes, fp32.
// out[b,k,c] = sum_n w[b,n,k]*(x[b,c,n]) - (sum_n w[b,n,k])*cw[k,c]
// w = softmax_k( scale[k] * (||x_bn||^2 - 2*<x_bn,c_k> + ||c_k||^2) )

#define Bn 32
#define Cc 256
#define Ntok 4096
#define Kk 32
#define Ss 16                 // splits per batch
#define LTOK (Ntok / Ss)      // 256 tokens per block
#define NT 64                 // tokens per tile
#define NTP 66                // padded token stride (2-way conflicts max)
#define WP 36                 // wsm row stride (float4-aligned, low conflict)
#define THREADS 256

#define SMEM_FLOATS (Cc*Kk + Cc*NTP + NT*WP + NT + 3*Kk)
#define SMEM_BYTES (SMEM_FLOATS * 4)

// deterministic partial buffers (no float atomics anywhere)
__device__ float g_part[Bn * Ss * Kk * Cc];   // 16 MB
__device__ float g_wsum[Bn * Ss * Kk];

__global__ __launch_bounds__(THREADS, 2)
void enc_main(const float* __restrict__ x,
              const float* __restrict__ cw,
              const float* __restrict__ scale)
{
    extern __shared__ float sm[];
    float* cwT    = sm;                  // [Cc][Kk]  codewords transposed, 128B rows
    float* xs     = cwT + Cc * Kk;       // [Cc][NTP] x tile, c-major
    float* wsm    = xs + Cc * NTP;       // [NT][WP]  logits -> weights
    float* xsq_s  = wsm + NT * WP;       // [NT]
    float* csq_s  = xsq_s + NT;          // [Kk]
    float* scl_s  = csq_s + Kk;          // [Kk]
    float* wsum_s = scl_s + Kk;          // [Kk]

    const int tid = threadIdx.x;
    const int s = blockIdx.x;
    const int b = blockIdx.y;

    // stage codewords transposed
    for (int i = tid; i < Kk * Cc; i += THREADS) {
        int k = i >> 8;          // i / Cc
        int c = i & (Cc - 1);
        cwT[c * Kk + k] = cw[i];
    }
    if (tid < Kk) { scl_s[tid] = scale[tid]; wsum_s[tid] = 0.f; }
    __syncthreads();
    if (tid < Kk) {
        float s2 = 0.f;
        #pragma unroll 8
        for (int c = 0; c < Cc; c++) { float v = cwT[c * Kk + tid]; s2 += v * v; }
        csq_s[tid] = s2;
    }

    // phase-2 accumulators: thread owns 8 k x 4 c, persistent over all tiles
    float acc[32];
    #pragma unroll
    for (int i = 0; i < 32; i++) acc[i] = 0.f;

    // phase-1 mapping: 2 n x 4 k per thread
    const int kq  = tid & 7;   const int k0a = kq * 4;
    const int np  = tid >> 3;  const int n0  = np * 2;
    // phase-2 mapping: 8 k x 4 c per thread (c strided by 64 -> 2-way max)
    const int kg  = tid >> 6;  const int k0b = kg * 8;
    const int ck  = tid & 63;

    const float* xb = x + (size_t)b * Cc * Ntok + s * LTOK;

    for (int t = 0; t < LTOK / NT; t++) {
        __syncthreads();   // previous tile's phase-2 readers done with xs/wsm

        // ---- load x tile: xs[c][n] = x[b][c][tok0+n] (coalesced 128B rows)
        const float* xt = xb + t * NT;
        #pragma unroll 4
        for (int i = tid; i < Cc * NT; i += THREADS) {
            int c = i >> 6;
            int n = i & 63;
            xs[c * NTP + n] = xt[c * Ntok + n];
        }
        __syncthreads();

        // ---- phase 1: xc[n][k] dots over C
        float r[2][4];
        #pragma unroll
        for (int i = 0; i < 2; i++)
            #pragma unroll
            for (int j = 0; j < 4; j++) r[i][j] = 0.f;
        {
            const float* ap = xs + n0;
            const float* bp = cwT + k0a;
            #pragma unroll 4
            for (int c = 0; c < Cc; c++) {
                float2 a  = *(const float2*)(ap + c * NTP);
                float4 bb = *(const float4*)(bp + c * Kk);
                r[0][0] += a.x * bb.x; r[0][1] += a.x * bb.y;
                r[0][2] += a.x * bb.z; r[0][3] += a.x * bb.w;
                r[1][0] += a.y * bb.x; r[1][1] += a.y * bb.y;
                r[1][2] += a.y * bb.z; r[1][3] += a.y * bb.w;
            }
        }
        // ---- ||x||^2 per token (exact fp32; enters exponent scaled by up to 1)
        if (tid < NT) {
            float s2 = 0.f;
            const float* col = xs + tid;
            #pragma unroll 8
            for (int c = 0; c < Cc; c++) { float v = col[c * NTP]; s2 += v * v; }
            xsq_s[tid] = s2;
        }
        __syncthreads();

        // ---- sl2 logits -> wsm
        {
            float xq0 = xsq_s[n0], xq1 = xsq_s[n0 + 1];
            float4 sc = *(const float4*)(scl_s + k0a);
            float4 cq = *(const float4*)(csq_s + k0a);
            float4 o0, o1;
            o0.x = sc.x * (xq0 - 2.f * r[0][0] + cq.x);
            o0.y = sc.y * (xq0 - 2.f * r[0][1] + cq.y);
            o0.z = sc.z * (xq0 - 2.f * r[0][2] + cq.z);
            o0.w = sc.w * (xq0 - 2.f * r[0][3] + cq.w);
            o1.x = sc.x * (xq1 - 2.f * r[1][0] + cq.x);
            o1.y = sc.y * (xq1 - 2.f * r[1][1] + cq.y);
            o1.z = sc.z * (xq1 - 2.f * r[1][2] + cq.z);
            o1.w = sc.w * (xq1 - 2.f * r[1][3] + cq.w);
            *(float4*)(wsm + n0 * WP + k0a)       = o0;
            *(float4*)(wsm + (n0 + 1) * WP + k0a) = o1;
        }
        __syncthreads();

        // ---- softmax over k, per token, in registers (max-subtracted)
        if (tid < NT) {
            float* row = wsm + tid * WP;
            float rv[Kk];
            #pragma unroll
            for (int k = 0; k < Kk; k++) rv[k] = row[k];
            float m = rv[0];
            #pragma unroll
            for (int k = 1; k < Kk; k++) m = fmaxf(m, rv[k]);
            float ssum = 0.f;
            #pragma unroll
            for (int k = 0; k < Kk; k++) { rv[k] = __expf(rv[k] - m); ssum += rv[k]; }
            float inv = 1.f / ssum;
            #pragma unroll
            for (int k = 0; k < Kk; k++) row[k] = rv[k] * inv;
        }
        __syncthreads();

        // ---- wsum[k] += sum_n w (single owner thread per k -> deterministic)
        if (tid < Kk) {
            float wl = 0.f;
            #pragma unroll 8
            for (int n = 0; n < NT; n++) wl += wsm[n * WP + tid];
            wsum_s[tid] += wl;
        }

        // ---- phase 2: acc[k][c] += w[n][k] * xs[c][n]
        {
            const float* xp = xs + ck * NTP;
            const float* wp = wsm + k0b;
            #pragma unroll 2
            for (int n = 0; n < NT; n++) {
                float4 w0 = *(const float4*)(wp + n * WP);
                float4 w1 = *(const float4*)(wp + n * WP + 4);
                float wv[8];
                wv[0] = w0.x; wv[1] = w0.y; wv[2] = w0.z; wv[3] = w0.w;
                wv[4] = w1.x; wv[5] = w1.y; wv[6] = w1.z; wv[7] = w1.w;
                float xv[4];
                xv[0] = xp[n];
                xv[1] = xp[64 * NTP + n];
                xv[2] = xp[128 * NTP + n];
                xv[3] = xp[192 * NTP + n];
                #pragma unroll
                for (int kk = 0; kk < 8; kk++)
                    #pragma unroll
                    for (int j = 0; j < 4; j++)
                        acc[kk * 4 + j] += wv[kk] * xv[j];
            }
        }
    }

    // ---- write block partials (coalesced per (kk,j) slice)
    {
        float* gp = g_part + (size_t)(b * Ss + s) * (Kk * Cc);
        #pragma unroll
        for (int kk = 0; kk < 8; kk++)
            #pragma unroll
            for (int j = 0; j < 4; j++)
                gp[(k0b + kk) * Cc + ck + 64 * j] = acc[kk * 4 + j];
        if (tid < Kk) g_wsum[(b * Ss + s) * Kk + tid] = wsum_s[tid];
    }
}

__global__ void enc_fin(const float* __restrict__ cw, float* __restrict__ out)
{
    int idx = blockIdx.x * blockDim.x + threadIdx.x;
    if (idx >= Bn * Kk * Cc) return;
    int c = idx & (Cc - 1);
    int k = (idx >> 8) & (Kk - 1);
    int b = idx >> 13;
    float sum = 0.f, ws = 0.f;
    #pragma unroll
    for (int s = 0; s < Ss; s++) {
        sum += g_part[(size_t)((b * Ss + s) * Kk + k) * Cc + c];
        ws  += g_wsum[(b * Ss + s) * Kk + k];
    }
    out[idx] = sum - ws * cw[k * Cc + c];
}

extern "C" void kernel_launch(void* const* d_in, const int* in_sizes, int n_in,
                              void* d_out, int out_size)
{
    const float* x     = (const float*)d_in[0];
    const float* cw    = (const float*)d_in[1];
    const float* scale = (const float*)d_in[2];
    float* out = (float*)d_out;

    // idempotent, deterministic; needed for >48KB dynamic smem
    cudaFuncSetAttribute(enc_main, cudaFuncAttributeMaxDynamicSharedMemorySize, SMEM_BYTES);

    dim3 grid(Ss, Bn);
    enc_main<<<grid, THREADS, SMEM_BYTES>>>(x, cw, scale);
    enc_fin<<<(Bn * Kk * Cc + 255) / 256, 256>>>(cw, out);
}

// round 5
// speedup vs baseline: 1.9963x; 1.9963x over previous
#include <cuda_runtime.h>
#include <cstdint>

// Encoding layer on tensor cores (tf32 mma.sync), B=32, C=256, N=4096, K=32.
// Phase 1: logits xc = x . cw^T   (single tf32; x_sq/c_sq exact fp32)
// Softmax in MMA D-fragments (registers + butterfly shuffles)
// Phase 2: wx = w^T . x with 3xTF32 split (hi/lo via 0xFFFFE000 mask) -> ~fp32 accuracy
// Deterministic: fixed split partials + fixed-order reductions, no float atomics.
// R3 fix: NTP 66 -> 68 (float4 stores into xs were misaligned at odd c);
//         g_part/g_wsum 16B-aligned for float4 access in enc_fin.

#define Bn 32
#define Cc 256
#define Ntok 4096
#define Kk 32
#define Ss 16
#define LTOK 256
#define NT 64
#define NTP 68
#define THREADS 128

#define TFMASK 0xFFFFE000u

__device__ __align__(16) float g_part[Bn * Ss * Kk * Cc];
__device__ __align__(16) float g_wsum[Bn * Ss * Kk];

__device__ __forceinline__ void mma_tf32(float& d0, float& d1, float& d2, float& d3,
                                         uint32_t a0, uint32_t a1, uint32_t a2, uint32_t a3,
                                         uint32_t b0, uint32_t b1)
{
    asm volatile("mma.sync.aligned.m16n8k8.row.col.f32.tf32.tf32.f32 "
                 "{%0,%1,%2,%3}, {%4,%5,%6,%7}, {%8,%9}, {%0,%1,%2,%3};"
                 : "+f"(d0), "+f"(d1), "+f"(d2), "+f"(d3)
                 : "r"(a0), "r"(a1), "r"(a2), "r"(a3), "r"(b0), "r"(b1));
}

// smem (floats): xs[Cc*NTP] | cwF[8192] | wT[Kk*NTP] | xsq[NT] | csq[Kk] | scl[Kk] | wsm4[4*Kk]
#define SMEM_FLOATS (Cc*NTP + 8192 + Kk*NTP + NT + Kk + Kk + 4*Kk)
#define SMEM_BYTES  (SMEM_FLOATS * 4)

__global__ __launch_bounds__(THREADS, 2)
void enc_main(const float* __restrict__ x,
              const float* __restrict__ cw,
              const float* __restrict__ scale)
{
    extern __shared__ float sm[];
    float* xs   = sm;
    float* cwF  = xs + Cc * NTP;
    float* wT   = cwF + 8192;
    float* xsq  = wT + Kk * NTP;
    float* csq  = xsq + NT;
    float* scl  = csq + Kk;
    float* wsm4 = scl + Kk;

    const int tid  = threadIdx.x;
    const int lane = tid & 31;
    const int warp = tid >> 5;
    const int g    = lane >> 2;   // groupID
    const int tg   = lane & 3;    // threadID_in_group
    const int b = blockIdx.y, s = blockIdx.x;

    // ---- build phase-1 B fragments: cwF[((cstep*4+nt)*32 + lane)*2 + r]
    //      = tf32(cw[k = nt*8 + lane/4][c = cstep*8 + lane%4 + r*4])
    for (int i = tid; i < 8192; i += THREADS) {
        int r = i & 1, j = i >> 1;
        int ln = j & 31, slot = j >> 5;
        int nt = slot & 3, cstep = slot >> 2;
        int k = nt * 8 + (ln >> 2);
        int c = cstep * 8 + (ln & 3) + r * 4;
        cwF[i] = __uint_as_float(__float_as_uint(cw[k * Cc + c]) & TFMASK);
    }
    if (tid < Kk) {
        float s2 = 0.f;
        const float4* cr = (const float4*)(cw + tid * Cc);
        #pragma unroll 8
        for (int c4 = 0; c4 < Cc / 4; c4++) {
            float4 v = cr[c4];
            s2 += v.x * v.x + v.y * v.y + v.z * v.z + v.w * v.w;
        }
        csq[tid] = s2;
        scl[tid] = scale[tid];
    }
    __syncthreads();

    // per-thread k constants: this thread's codes are k = nt*8 + 2*tg + j
    float sck[4][2], sqk[4][2];
    #pragma unroll
    for (int nt = 0; nt < 4; nt++)
        #pragma unroll
        for (int j = 0; j < 2; j++) {
            int k = nt * 8 + 2 * tg + j;
            sck[nt][j] = scl[k];
            sqk[nt][j] = scl[k] * csq[k];
        }

    float wacc[8];
    #pragma unroll
    for (int i = 0; i < 8; i++) wacc[i] = 0.f;

    float acc2[2][8][4];
    #pragma unroll
    for (int mt = 0; mt < 2; mt++)
        #pragma unroll
        for (int nt = 0; nt < 8; nt++)
            #pragma unroll
            for (int r = 0; r < 4; r++) acc2[mt][nt][r] = 0.f;

    const float* xb = x + (size_t)b * Cc * Ntok + s * LTOK;
    const int c0 = warp * 64;   // phase-2 channel slice
    const int nb = warp * 16;   // phase-1 token m-tile

    for (int t = 0; t < LTOK / NT; t++) {
        __syncthreads();   // previous tile's readers done

        // ---- load x tile [Cc][NT] (coalesced float4)
        const float* xt = xb + t * NT;
        for (int i = tid; i < Cc * NT / 4; i += THREADS) {
            int c = i >> 4, v = i & 15;
            float4 val = *(const float4*)(xt + c * Ntok + v * 4);
            *(float4*)(xs + c * NTP + v * 4) = val;
        }
        __syncthreads();

        // ---- x_sq (exact fp32): 2 threads per token
        {
            int n = tid >> 1, ch = (tid & 1) << 7;
            float s2 = 0.f;
            #pragma unroll 8
            for (int c = 0; c < 128; c++) { float v = xs[(ch + c) * NTP + n]; s2 += v * v; }
            s2 += __shfl_xor_sync(0xffffffffu, s2, 1);
            if ((tid & 1) == 0) xsq[n] = s2;
        }

        // ---- phase 1: warp's 16 tokens x all 32 codes, contraction over C
        float p1[4][4];
        #pragma unroll
        for (int nt = 0; nt < 4; nt++)
            #pragma unroll
            for (int r = 0; r < 4; r++) p1[nt][r] = 0.f;

        #pragma unroll 4
        for (int cs = 0; cs < 32; cs++) {
            uint32_t a0 = __float_as_uint(xs[(cs * 8 + tg) * NTP + nb + g]);
            uint32_t a1 = __float_as_uint(xs[(cs * 8 + tg) * NTP + nb + g + 8]);
            uint32_t a2 = __float_as_uint(xs[(cs * 8 + tg + 4) * NTP + nb + g]);
            uint32_t a3 = __float_as_uint(xs[(cs * 8 + tg + 4) * NTP + nb + g + 8]);
            #pragma unroll
            for (int nt = 0; nt < 4; nt++) {
                float2 bb = *(const float2*)(cwF + ((cs * 4 + nt) * 32 + lane) * 2);
                mma_tf32(p1[nt][0], p1[nt][1], p1[nt][2], p1[nt][3],
                         a0, a1, a2, a3,
                         __float_as_uint(bb.x), __float_as_uint(bb.y));
            }
        }
        __syncthreads();   // xsq visible to all

        // ---- logits + softmax in registers
        {
            float xq0 = xsq[nb + g], xq1 = xsq[nb + g + 8];
            float wv[4][4];
            float m0 = -1e30f, m1 = -1e30f;
            #pragma unroll
            for (int nt = 0; nt < 4; nt++) {
                wv[nt][0] = sck[nt][0] * fmaf(-2.f, p1[nt][0], xq0) + sqk[nt][0];
                wv[nt][1] = sck[nt][1] * fmaf(-2.f, p1[nt][1], xq0) + sqk[nt][1];
                wv[nt][2] = sck[nt][0] * fmaf(-2.f, p1[nt][2], xq1) + sqk[nt][0];
                wv[nt][3] = sck[nt][1] * fmaf(-2.f, p1[nt][3], xq1) + sqk[nt][1];
                m0 = fmaxf(m0, fmaxf(wv[nt][0], wv[nt][1]));
                m1 = fmaxf(m1, fmaxf(wv[nt][2], wv[nt][3]));
            }
            m0 = fmaxf(m0, __shfl_xor_sync(0xffffffffu, m0, 1));
            m0 = fmaxf(m0, __shfl_xor_sync(0xffffffffu, m0, 2));
            m1 = fmaxf(m1, __shfl_xor_sync(0xffffffffu, m1, 1));
            m1 = fmaxf(m1, __shfl_xor_sync(0xffffffffu, m1, 2));
            float s0 = 0.f, s1 = 0.f;
            #pragma unroll
            for (int nt = 0; nt < 4; nt++) {
                wv[nt][0] = __expf(wv[nt][0] - m0); s0 += wv[nt][0];
                wv[nt][1] = __expf(wv[nt][1] - m0); s0 += wv[nt][1];
                wv[nt][2] = __expf(wv[nt][2] - m1); s1 += wv[nt][2];
                wv[nt][3] = __expf(wv[nt][3] - m1); s1 += wv[nt][3];
            }
            s0 += __shfl_xor_sync(0xffffffffu, s0, 1);
            s0 += __shfl_xor_sync(0xffffffffu, s0, 2);
            s1 += __shfl_xor_sync(0xffffffffu, s1, 1);
            s1 += __shfl_xor_sync(0xffffffffu, s1, 2);
            float i0 = 1.f / s0, i1 = 1.f / s1;
            #pragma unroll
            for (int nt = 0; nt < 4; nt++) {
                wv[nt][0] *= i0; wv[nt][1] *= i0;
                wv[nt][2] *= i1; wv[nt][3] *= i1;
                wacc[nt * 2 + 0] += wv[nt][0] + wv[nt][2];
                wacc[nt * 2 + 1] += wv[nt][1] + wv[nt][3];
                int k0_ = nt * 8 + 2 * tg;
                wT[k0_ * NTP + nb + g]           = wv[nt][0];
                wT[(k0_ + 1) * NTP + nb + g]     = wv[nt][1];
                wT[k0_ * NTP + nb + g + 8]       = wv[nt][2];
                wT[(k0_ + 1) * NTP + nb + g + 8] = wv[nt][3];
            }
        }
        __syncthreads();   // wT ready

        // ---- phase 2: acc[k][c] += w^T x, contraction over tokens, 3xTF32
        for (int ns = 0; ns < 8; ns++) {
            uint32_t whi[2][4], wlo[2][4];
            #pragma unroll
            for (int mt = 0; mt < 2; mt++)
                #pragma unroll
                for (int r = 0; r < 4; r++) {
                    int kk = mt * 16 + g + (r & 1) * 8;
                    int nn = ns * 8 + tg + (r >> 1) * 4;
                    float f = wT[kk * NTP + nn];
                    uint32_t h = __float_as_uint(f) & TFMASK;
                    whi[mt][r] = h;
                    wlo[mt][r] = __float_as_uint(f - __uint_as_float(h));
                }
            #pragma unroll
            for (int nt = 0; nt < 8; nt++) {
                int cc = c0 + nt * 8 + g;
                float f0 = xs[cc * NTP + ns * 8 + tg];
                float f1 = xs[cc * NTP + ns * 8 + tg + 4];
                uint32_t h0 = __float_as_uint(f0) & TFMASK;
                uint32_t h1 = __float_as_uint(f1) & TFMASK;
                uint32_t l0 = __float_as_uint(f0 - __uint_as_float(h0));
                uint32_t l1 = __float_as_uint(f1 - __uint_as_float(h1));
                #pragma unroll
                for (int mt = 0; mt < 2; mt++) {
                    mma_tf32(acc2[mt][nt][0], acc2[mt][nt][1], acc2[mt][nt][2], acc2[mt][nt][3],
                             whi[mt][0], whi[mt][1], whi[mt][2], whi[mt][3], h0, h1);
                    mma_tf32(acc2[mt][nt][0], acc2[mt][nt][1], acc2[mt][nt][2], acc2[mt][nt][3],
                             wlo[mt][0], wlo[mt][1], wlo[mt][2], wlo[mt][3], h0, h1);
                    mma_tf32(acc2[mt][nt][0], acc2[mt][nt][1], acc2[mt][nt][2], acc2[mt][nt][3],
                             whi[mt][0], whi[mt][1], whi[mt][2], whi[mt][3], l0, l1);
                }
            }
        }
    }

    // ---- write partials (float2, deterministic)
    {
        float* gp = g_part + (size_t)(b * Ss + s) * (Kk * Cc);
        #pragma unroll
        for (int mt = 0; mt < 2; mt++)
            #pragma unroll
            for (int nt = 0; nt < 8; nt++) {
                int kk = mt * 16 + g;
                int cc = c0 + nt * 8 + 2 * tg;
                *(float2*)(gp + kk * Cc + cc)       = make_float2(acc2[mt][nt][0], acc2[mt][nt][1]);
                *(float2*)(gp + (kk + 8) * Cc + cc) = make_float2(acc2[mt][nt][2], acc2[mt][nt][3]);
            }
    }
    // ---- wsum: reduce across g-lanes, then across warps (fixed order)
    #pragma unroll
    for (int i = 0; i < 8; i++) {
        wacc[i] += __shfl_xor_sync(0xffffffffu, wacc[i], 4);
        wacc[i] += __shfl_xor_sync(0xffffffffu, wacc[i], 8);
        wacc[i] += __shfl_xor_sync(0xffffffffu, wacc[i], 16);
    }
    if (g == 0) {
        #pragma unroll
        for (int nt = 0; nt < 4; nt++) {
            wsm4[warp * Kk + nt * 8 + 2 * tg + 0] = wacc[nt * 2 + 0];
            wsm4[warp * Kk + nt * 8 + 2 * tg + 1] = wacc[nt * 2 + 1];
        }
    }
    __syncthreads();
    if (tid < Kk)
        g_wsum[(b * Ss + s) * Kk + tid] =
            wsm4[tid] + wsm4[Kk + tid] + wsm4[2 * Kk + tid] + wsm4[3 * Kk + tid];
}

__global__ void enc_fin(const float* __restrict__ cw, float* __restrict__ out)
{
    int idx = blockIdx.x * blockDim.x + threadIdx.x;   // over B*K*C/4
    if (idx >= Bn * Kk * Cc / 4) return;
    int c4 = idx & 63;
    int k  = (idx >> 6) & 31;
    int b  = idx >> 11;
    float4 sum = make_float4(0.f, 0.f, 0.f, 0.f);
    float ws = 0.f;
    #pragma unroll
    for (int s = 0; s < Ss; s++) {
        const float4 p = *(const float4*)(g_part + ((size_t)((b * Ss + s) * Kk + k)) * Cc + c4 * 4);
        sum.x += p.x; sum.y += p.y; sum.z += p.z; sum.w += p.w;
        ws += g_wsum[(b * Ss + s) * Kk + k];
    }
    float4 cv = *(const float4*)(cw + k * Cc + c4 * 4);
    float4 o;
    o.x = sum.x - ws * cv.x;
    o.y = sum.y - ws * cv.y;
    o.z = sum.z - ws * cv.z;
    o.w = sum.w - ws * cv.w;
    *(float4*)(out + (size_t)idx * 4) = o;
}

extern "C" void kernel_launch(void* const* d_in, const int* in_sizes, int n_in,
                              void* d_out, int out_size)
{
    const float* x     = (const float*)d_in[0];
    const float* cw    = (const float*)d_in[1];
    const float* scale = (const float*)d_in[2];
    float* out = (float*)d_out;

    cudaFuncSetAttribute(enc_main, cudaFuncAttributeMaxDynamicSharedMemorySize, SMEM_BYTES);

    dim3 grid(Ss, Bn);
    enc_main<<<grid, THREADS, SMEM_BYTES>>>(x, cw, scale);
    enc_fin<<<(Bn * Kk * Cc / 4 + 255) / 256, 256>>>(cw, out);
}

// round 6
// speedup vs baseline: 2.0606x; 1.0322x over previous
#include <cuda_runtime.h>
#include <cstdint>

// Encoding layer on tensor cores (tf32 mma.sync), B=32, C=256, N=4096, K=32.
// Phase 1: logits xc = x . cw^T (single tf32; x_sq/c_sq exact fp32)
// Softmax in MMA D-fragments; Phase 2: wx = w^T.x with 3xTF32 split.
// R5: enc_fin fused into enc_main via last-block-per-batch counter (deterministic,
//     self-resetting); Ss 16 -> 8 (single wave, half partial traffic).

#define Bn 32
#define Cc 256
#define Ntok 4096
#define Kk 32
#define Ss 8
#define LTOK (Ntok / Ss)
#define NT 64
#define NTP 68
#define THREADS 128

#define TFMASK 0xFFFFE000u

__device__ __align__(16) float g_part[Bn * Ss * Kk * Cc];
__device__ __align__(16) float g_wsum[Bn * Ss * Kk];
__device__ int g_cnt[Bn];   // zero-initialized at module load; self-reset each launch

__device__ __forceinline__ void mma_tf32(float& d0, float& d1, float& d2, float& d3,
                                         uint32_t a0, uint32_t a1, uint32_t a2, uint32_t a3,
                                         uint32_t b0, uint32_t b1)
{
    asm volatile("mma.sync.aligned.m16n8k8.row.col.f32.tf32.tf32.f32 "
                 "{%0,%1,%2,%3}, {%4,%5,%6,%7}, {%8,%9}, {%0,%1,%2,%3};"
                 : "+f"(d0), "+f"(d1), "+f"(d2), "+f"(d3)
                 : "r"(a0), "r"(a1), "r"(a2), "r"(a3), "r"(b0), "r"(b1));
}

// smem (floats): xs[Cc*NTP] | cwF[8192] | wT[Kk*NTP] | xsq[NT] | csq[Kk] | scl[Kk] | wsm4[4*Kk]
#define SMEM_FLOATS (Cc*NTP + 8192 + Kk*NTP + NT + Kk + Kk + 4*Kk)
#define SMEM_BYTES  (SMEM_FLOATS * 4)

__global__ __launch_bounds__(THREADS, 2)
void enc_main(const float* __restrict__ x,
              const float* __restrict__ cw,
              const float* __restrict__ scale,
              float* __restrict__ out)
{
    extern __shared__ float sm[];
    float* xs   = sm;
    float* cwF  = xs + Cc * NTP;
    float* wT   = cwF + 8192;
    float* xsq  = wT + Kk * NTP;
    float* csq  = xsq + NT;
    float* scl  = csq + Kk;
    float* wsm4 = scl + Kk;
    __shared__ int isLast;

    const int tid  = threadIdx.x;
    const int lane = tid & 31;
    const int warp = tid >> 5;
    const int g    = lane >> 2;   // groupID
    const int tg   = lane & 3;    // threadID_in_group
    const int b = blockIdx.y, s = blockIdx.x;

    // ---- build phase-1 B fragments: cwF[((cstep*4+nt)*32 + lane)*2 + r]
    //      = tf32(cw[k = nt*8 + lane/4][c = cstep*8 + lane%4 + r*4])
    for (int i = tid; i < 8192; i += THREADS) {
        int r = i & 1, j = i >> 1;
        int ln = j & 31, slot = j >> 5;
        int nt = slot & 3, cstep = slot >> 2;
        int k = nt * 8 + (ln >> 2);
        int c = cstep * 8 + (ln & 3) + r * 4;
        cwF[i] = __uint_as_float(__float_as_uint(cw[k * Cc + c]) & TFMASK);
    }
    if (tid < Kk) {
        float s2 = 0.f;
        const float4* cr = (const float4*)(cw + tid * Cc);
        #pragma unroll 8
        for (int c4 = 0; c4 < Cc / 4; c4++) {
            float4 v = cr[c4];
            s2 += v.x * v.x + v.y * v.y + v.z * v.z + v.w * v.w;
        }
        csq[tid] = s2;
        scl[tid] = scale[tid];
    }
    __syncthreads();

    // per-thread k constants: this thread's codes are k = nt*8 + 2*tg + j
    float sck[4][2], sqk[4][2];
    #pragma unroll
    for (int nt = 0; nt < 4; nt++)
        #pragma unroll
        for (int j = 0; j < 2; j++) {
            int k = nt * 8 + 2 * tg + j;
            sck[nt][j] = scl[k];
            sqk[nt][j] = scl[k] * csq[k];
        }

    float wacc[8];
    #pragma unroll
    for (int i = 0; i < 8; i++) wacc[i] = 0.f;

    float acc2[2][8][4];
    #pragma unroll
    for (int mt = 0; mt < 2; mt++)
        #pragma unroll
        for (int nt = 0; nt < 8; nt++)
            #pragma unroll
            for (int r = 0; r < 4; r++) acc2[mt][nt][r] = 0.f;

    const float* xb = x + (size_t)b * Cc * Ntok + s * LTOK;
    const int c0 = warp * 64;   // phase-2 channel slice
    const int nb = warp * 16;   // phase-1 token m-tile

    for (int t = 0; t < LTOK / NT; t++) {
        __syncthreads();   // previous tile's readers done

        // ---- load x tile [Cc][NT] (coalesced float4)
        const float* xt = xb + t * NT;
        for (int i = tid; i < Cc * NT / 4; i += THREADS) {
            int c = i >> 4, v = i & 15;
            float4 val = *(const float4*)(xt + c * Ntok + v * 4);
            *(float4*)(xs + c * NTP + v * 4) = val;
        }
        __syncthreads();

        // ---- x_sq (exact fp32): 2 threads per token
        {
            int n = tid >> 1, ch = (tid & 1) << 7;
            float s2 = 0.f;
            #pragma unroll 8
            for (int c = 0; c < 128; c++) { float v = xs[(ch + c) * NTP + n]; s2 += v * v; }
            s2 += __shfl_xor_sync(0xffffffffu, s2, 1);
            if ((tid & 1) == 0) xsq[n] = s2;
        }

        // ---- phase 1: warp's 16 tokens x all 32 codes, contraction over C
        float p1[4][4];
        #pragma unroll
        for (int nt = 0; nt < 4; nt++)
            #pragma unroll
            for (int r = 0; r < 4; r++) p1[nt][r] = 0.f;

        #pragma unroll 4
        for (int cs = 0; cs < 32; cs++) {
            uint32_t a0 = __float_as_uint(xs[(cs * 8 + tg) * NTP + nb + g]);
            uint32_t a1 = __float_as_uint(xs[(cs * 8 + tg) * NTP + nb + g + 8]);
            uint32_t a2 = __float_as_uint(xs[(cs * 8 + tg + 4) * NTP + nb + g]);
            uint32_t a3 = __float_as_uint(xs[(cs * 8 + tg + 4) * NTP + nb + g + 8]);
            #pragma unroll
            for (int nt = 0; nt < 4; nt++) {
                float2 bb = *(const float2*)(cwF + ((cs * 4 + nt) * 32 + lane) * 2);
                mma_tf32(p1[nt][0], p1[nt][1], p1[nt][2], p1[nt][3],
                         a0, a1, a2, a3,
                         __float_as_uint(bb.x), __float_as_uint(bb.y));
            }
        }
        __syncthreads();   // xsq visible to all

        // ---- logits + softmax in registers
        {
            float xq0 = xsq[nb + g], xq1 = xsq[nb + g + 8];
            float wv[4][4];
            float m0 = -1e30f, m1 = -1e30f;
            #pragma unroll
            for (int nt = 0; nt < 4; nt++) {
                wv[nt][0] = sck[nt][0] * fmaf(-2.f, p1[nt][0], xq0) + sqk[nt][0];
                wv[nt][1] = sck[nt][1] * fmaf(-2.f, p1[nt][1], xq0) + sqk[nt][1];
                wv[nt][2] = sck[nt][0] * fmaf(-2.f, p1[nt][2], xq1) + sqk[nt][0];
                wv[nt][3] = sck[nt][1] * fmaf(-2.f, p1[nt][3], xq1) + sqk[nt][1];
                m0 = fmaxf(m0, fmaxf(wv[nt][0], wv[nt][1]));
                m1 = fmaxf(m1, fmaxf(wv[nt][2], wv[nt][3]));
            }
            m0 = fmaxf(m0, __shfl_xor_sync(0xffffffffu, m0, 1));
            m0 = fmaxf(m0, __shfl_xor_sync(0xffffffffu, m0, 2));
            m1 = fmaxf(m1, __shfl_xor_sync(0xffffffffu, m1, 1));
            m1 = fmaxf(m1, __shfl_xor_sync(0xffffffffu, m1, 2));
            float s0 = 0.f, s1 = 0.f;
            #pragma unroll
            for (int nt = 0; nt < 4; nt++) {
                wv[nt][0] = __expf(wv[nt][0] - m0); s0 += wv[nt][0];
                wv[nt][1] = __expf(wv[nt][1] - m0); s0 += wv[nt][1];
                wv[nt][2] = __expf(wv[nt][2] - m1); s1 += wv[nt][2];
                wv[nt][3] = __expf(wv[nt][3] - m1); s1 += wv[nt][3];
            }
            s0 += __shfl_xor_sync(0xffffffffu, s0, 1);
            s0 += __shfl_xor_sync(0xffffffffu, s0, 2);
            s1 += __shfl_xor_sync(0xffffffffu, s1, 1);
            s1 += __shfl_xor_sync(0xffffffffu, s1, 2);
            float i0 = 1.f / s0, i1 = 1.f / s1;
            #pragma unroll
            for (int nt = 0; nt < 4; nt++) {
                wv[nt][0] *= i0; wv[nt][1] *= i0;
                wv[nt][2] *= i1; wv[nt][3] *= i1;
                wacc[nt * 2 + 0] += wv[nt][0] + wv[nt][2];
                wacc[nt * 2 + 1] += wv[nt][1] + wv[nt][3];
                int k0_ = nt * 8 + 2 * tg;
                wT[k0_ * NTP + nb + g]           = wv[nt][0];
                wT[(k0_ + 1) * NTP + nb + g]     = wv[nt][1];
                wT[k0_ * NTP + nb + g + 8]       = wv[nt][2];
                wT[(k0_ + 1) * NTP + nb + g + 8] = wv[nt][3];
            }
        }
        __syncthreads();   // wT ready

        // ---- phase 2: acc[k][c] += w^T x, contraction over tokens, 3xTF32
        for (int ns = 0; ns < 8; ns++) {
            uint32_t whi[2][4], wlo[2][4];
            #pragma unroll
            for (int mt = 0; mt < 2; mt++)
                #pragma unroll
                for (int r = 0; r < 4; r++) {
                    int kk = mt * 16 + g + (r & 1) * 8;
                    int nn = ns * 8 + tg + (r >> 1) * 4;
                    float f = wT[kk * NTP + nn];
                    uint32_t h = __float_as_uint(f) & TFMASK;
                    whi[mt][r] = h;
                    wlo[mt][r] = __float_as_uint(f - __uint_as_float(h));
                }
            #pragma unroll
            for (int nt = 0; nt < 8; nt++) {
                int cc = c0 + nt * 8 + g;
                float f0 = xs[cc * NTP + ns * 8 + tg];
                float f1 = xs[cc * NTP + ns * 8 + tg + 4];
                uint32_t h0 = __float_as_uint(f0) & TFMASK;
                uint32_t h1 = __float_as_uint(f1) & TFMASK;
                uint32_t l0 = __float_as_uint(f0 - __uint_as_float(h0));
                uint32_t l1 = __float_as_uint(f1 - __uint_as_float(h1));
                #pragma unroll
                for (int mt = 0; mt < 2; mt++) {
                    mma_tf32(acc2[mt][nt][0], acc2[mt][nt][1], acc2[mt][nt][2], acc2[mt][nt][3],
                             whi[mt][0], whi[mt][1], whi[mt][2], whi[mt][3], h0, h1);
                    mma_tf32(acc2[mt][nt][0], acc2[mt][nt][1], acc2[mt][nt][2], acc2[mt][nt][3],
                             wlo[mt][0], wlo[mt][1], wlo[mt][2], wlo[mt][3], h0, h1);
                    mma_tf32(acc2[mt][nt][0], acc2[mt][nt][1], acc2[mt][nt][2], acc2[mt][nt][3],
                             whi[mt][0], whi[mt][1], whi[mt][2], whi[mt][3], l0, l1);
                }
            }
        }
    }

    // ---- write partials (float2, deterministic)
    {
        float* gp = g_part + (size_t)(b * Ss + s) * (Kk * Cc);
        #pragma unroll
        for (int mt = 0; mt < 2; mt++)
            #pragma unroll
            for (int nt = 0; nt < 8; nt++) {
                int kk = mt * 16 + g;
                int cc = c0 + nt * 8 + 2 * tg;
                *(float2*)(gp + kk * Cc + cc)       = make_float2(acc2[mt][nt][0], acc2[mt][nt][1]);
                *(float2*)(gp + (kk + 8) * Cc + cc) = make_float2(acc2[mt][nt][2], acc2[mt][nt][3]);
            }
    }
    // ---- wsum: reduce across g-lanes, then across warps (fixed order)
    #pragma unroll
    for (int i = 0; i < 8; i++) {
        wacc[i] += __shfl_xor_sync(0xffffffffu, wacc[i], 4);
        wacc[i] += __shfl_xor_sync(0xffffffffu, wacc[i], 8);
        wacc[i] += __shfl_xor_sync(0xffffffffu, wacc[i], 16);
    }
    if (g == 0) {
        #pragma unroll
        for (int nt = 0; nt < 4; nt++) {
            wsm4[warp * Kk + nt * 8 + 2 * tg + 0] = wacc[nt * 2 + 0];
            wsm4[warp * Kk + nt * 8 + 2 * tg + 1] = wacc[nt * 2 + 1];
        }
    }
    __syncthreads();
    if (tid < Kk)
        g_wsum[(b * Ss + s) * Kk + tid] =
            wsm4[tid] + wsm4[Kk + tid] + wsm4[2 * Kk + tid] + wsm4[3 * Kk + tid];

    // ==== finalize: last block per batch reduces the Ss partials ====
    __threadfence();
    __syncthreads();          // all partial writes issued before the count
    if (tid == 0)
        isLast = (atomicAdd(&g_cnt[b], 1) == Ss - 1);
    __syncthreads();
    if (!isLast) return;
    __threadfence();          // acquire: other blocks' writes now visible

    // wsum totals (fixed order over s)
    if (tid < Kk) {
        float w = 0.f;
        #pragma unroll
        for (int s2 = 0; s2 < Ss; s2++) w += g_wsum[(b * Ss + s2) * Kk + tid];
        xsq[tid] = w;   // reuse xsq smem
    }
    __syncthreads();

    const float* gpb = g_part + (size_t)b * Ss * Kk * Cc;
    float* ob = out + (size_t)b * Kk * Cc;
    for (int i = tid; i < Kk * Cc / 4; i += THREADS) {
        int k  = i >> 6;
        int c4 = i & 63;
        float4 sum = make_float4(0.f, 0.f, 0.f, 0.f);
        #pragma unroll
        for (int s2 = 0; s2 < Ss; s2++) {
            float4 p = *(const float4*)(gpb + (size_t)(s2 * Kk + k) * Cc + c4 * 4);
            sum.x += p.x; sum.y += p.y; sum.z += p.z; sum.w += p.w;
        }
        float ws = xsq[k];
        float4 cv = *(const float4*)(cw + k * Cc + c4 * 4);
        float4 o;
        o.x = sum.x - ws * cv.x;
        o.y = sum.y - ws * cv.y;
        o.z = sum.z - ws * cv.z;
        o.w = sum.w - ws * cv.w;
        *(float4*)(ob + i * 4) = o;
    }
    __syncthreads();
    if (tid == 0) g_cnt[b] = 0;   // self-reset for next launch/replay
}

extern "C" void kernel_launch(void* const* d_in, const int* in_sizes, int n_in,
                              void* d_out, int out_size)
{
    const float* x     = (const float*)d_in[0];
    const float* cw    = (const float*)d_in[1];
    const float* scale = (const float*)d_in[2];
    float* out = (float*)d_out;

    cudaFuncSetAttribute(enc_main, cudaFuncAttributeMaxDynamicSharedMemorySize, SMEM_BYTES);

    dim3 grid(Ss, Bn);
    enc_main<<<grid, THREADS, SMEM_BYTES>>>(x, cw, scale, out);
}